// round 1
// baseline (speedup 1.0000x reference)
#include <cuda_runtime.h>
#include <math.h>

#define BATCH 128
#define TT    127
#define SS    128
#define DIN   48
#define DKD   128
#define HH    8
#define LL    6
#define PP    8128
#define LHN   48
#define BS    (BATCH*SS)     /* 16384 */
#define BSD   (BS*DKD)       /* 2097152 */

typedef unsigned long long ull;

// ---------------- scratch (static device allocations; no runtime alloc) ----
__device__ float g_h[BSD];
__device__ float g_u[BSD];
__device__ float g_nrm[BS];
__device__ float g_cosv[LHN*PP];
__device__ float g_sinv[LHN*PP];
__device__ float g_W[LHN*DKD*DKD];
__device__ float g_T1[(size_t)HH*BSD];
__device__ float g_V [(size_t)HH*BSD];
__device__ float g_Pm[(size_t)HH*BS*SS];
__device__ float g_hs[(size_t)HH*BSD];

// ---------------- embed + class token + LN0 --------------------------------
__global__ void k_embed(const float* __restrict__ x, const float* __restrict__ ew,
                        const float* __restrict__ eb, const float* __restrict__ ct,
                        const float* __restrict__ g0, const float* __restrict__ b0)
{
    int bx = blockIdx.x;
    int b = bx >> 7, s = bx & 127;
    int d = threadIdx.x;
    __shared__ float xs[DIN];
    __shared__ float red[8];
    float v;
    if (s == 0) {
        v = ct[d];
    } else {
        if (d < DIN) xs[d] = x[(b*TT + (s-1))*DIN + d];
        __syncthreads();
        float acc = eb[d];
        const float* wrow = ew + d*DIN;
#pragma unroll
        for (int f = 0; f < DIN; f++) acc += xs[f]*wrow[f];
        v = acc;
    }
    float sum = v, sq = v*v;
#pragma unroll
    for (int o = 16; o; o >>= 1) {
        sum += __shfl_xor_sync(0xffffffffu, sum, o);
        sq  += __shfl_xor_sync(0xffffffffu, sq,  o);
    }
    if ((d & 31) == 0) { red[d>>5] = sum; red[4 + (d>>5)] = sq; }
    __syncthreads();
    float ts = red[0]+red[1]+red[2]+red[3];
    float tq = red[4]+red[5]+red[6]+red[7];
    float mean = ts * (1.0f/DKD);
    float var  = tq * (1.0f/DKD) - mean*mean;
    float inv  = rsqrtf(var + 1e-5f);
    g_h[(size_t)bx*DKD + d] = (v - mean)*inv*g0[d] + b0[d];
}

// ---------------- sincos precompute ----------------------------------------
__global__ void k_cs(const float* __restrict__ phi)
{
    int i = blockIdx.x*blockDim.x + threadIdx.x;
    if (i < LHN*PP) {
        float s, c;
        sincosf(phi[i], &s, &c);
        g_cosv[i] = c; g_sinv[i] = s;
    }
}

// ---------------- W build: brick-wall reordered Givens pyramid --------------
// rotation (k,i) (pair rows i,i+1) scheduled at time t=2k-i; disjoint within t.
__global__ __launch_bounds__(256) void k_wbuild()
{
    int lh = blockIdx.x, cg = blockIdx.y;      // 48 x 4
    __shared__ float Wsh[SS][33];
    int tid = threadIdx.x;
    int col = tid & 31, slot = tid >> 5;
    for (int idx = tid; idx < SS*32; idx += 256) {
        int r = idx >> 5, c = idx & 31;
        Wsh[r][c] = (r == cg*32 + c) ? 1.0f : 0.0f;
    }
    __syncthreads();
    const float* cb = g_cosv + lh*PP;
    const float* sb = g_sinv + lh*PP;
    for (int t = 0; t <= 2*(SS-2); t++) {
        int par  = t & 1;
        int imax = min(t, 2*(SS-2) - t);
        int cnt  = ((imax - par) >> 1) + 1;
        for (int r = slot; r < cnt; r += 8) {
            int i = par + 2*r;
            int k = (t + i) >> 1;
            int p = ((k*(k+1)) >> 1) + k - i;
            float c = cb[p], s = sb[p];
            float ra = Wsh[i][col], rb = Wsh[i+1][col];
            Wsh[i][col]   = c*ra - s*rb;
            Wsh[i+1][col] = s*ra + c*rb;
        }
        __syncthreads();
    }
    float* wp = g_W + (size_t)lh*DKD*DKD;
    for (int idx = tid; idx < SS*32; idx += 256) {
        int r = idx >> 5, c = idx & 31;
        wp[r*DKD + cg*32 + c] = Wsh[r][c];
    }
}

// ---------------- per-layer token norms -------------------------------------
__global__ void k_norm()
{
    int row = blockIdx.x;
    int d = threadIdx.x;
    float v = g_h[(size_t)row*DKD + d];
    float sq = v*v;
#pragma unroll
    for (int o = 16; o; o >>= 1) sq += __shfl_xor_sync(0xffffffffu, sq, o);
    __shared__ float red[4];
    if ((d & 31) == 0) red[d>>5] = sq;
    __syncthreads();
    float nrm = sqrtf(red[0]+red[1]+red[2]+red[3]);
    g_u[(size_t)row*DKD + d] = v / nrm;
    if (d == 0) g_nrm[row] = nrm;
}

// ---------------- 128x128x128 fp32 GEMM core (packed f32x2 FFMA2) ----------
template<bool TRANSB>
__device__ __forceinline__ void gemm128(const float* __restrict__ A,
                                        const float* __restrict__ Bp,
                                        float (*As)[132], float (*Bs)[132],
                                        ull acc[8][4], int tid)
{
    int tx = tid & 15, ty = tid >> 4;
    int lr = tid >> 1;
    int lk = (tid & 1) * 4;
#pragma unroll 1
    for (int kc = 0; kc < 16; kc++) {
        int k0 = kc*8;
        float4 av = *(const float4*)(A + lr*DKD + k0 + lk);
        float4 bv;
        if (TRANSB) bv = *(const float4*)(Bp + lr*DKD + k0 + lk);
        else        bv = *(const float4*)(Bp + (k0 + (tid>>5))*DKD + (tid&31)*4);
        __syncthreads();
        As[lk+0][lr]=av.x; As[lk+1][lr]=av.y; As[lk+2][lr]=av.z; As[lk+3][lr]=av.w;
        if (TRANSB) { Bs[lk+0][lr]=bv.x; Bs[lk+1][lr]=bv.y; Bs[lk+2][lr]=bv.z; Bs[lk+3][lr]=bv.w; }
        else        { *(float4*)&Bs[tid>>5][(tid&31)*4] = bv; }
        __syncthreads();
#pragma unroll
        for (int k = 0; k < 8; k++) {
            float a[8];
            *(float4*)&a[0] = *(const float4*)&As[k][ty*8];
            *(float4*)&a[4] = *(const float4*)&As[k][ty*8+4];
            ull b2[4];
            const ull* bptr = (const ull*)&Bs[k][tx*8];
            b2[0]=bptr[0]; b2[1]=bptr[1]; b2[2]=bptr[2]; b2[3]=bptr[3];
#pragma unroll
            for (int i = 0; i < 8; i++) {
                ull a2;
                asm("mov.b64 %0, {%1, %1};" : "=l"(a2) : "f"(a[i]));
#pragma unroll
                for (int q = 0; q < 4; q++)
                    asm("fma.rn.f32x2 %0, %1, %2, %0;" : "+l"(acc[i][q]) : "l"(a2), "l"(b2[q]));
            }
        }
    }
}

__device__ __forceinline__ void unpack2(ull v, float& lo, float& hi)
{
    asm("mov.b64 {%0, %1}, %2;" : "=f"(lo), "=f"(hi) : "l"(v));
}

// ---------------- T1 = u @ W[l,h]  (NN) ------------------------------------
__global__ __launch_bounds__(256,1) void k_t1(int l)
{
    __shared__ float As[8][132], Bs[8][132];
    int tid = threadIdx.x;
    int m0 = blockIdx.x * 128;
    int h = blockIdx.y;
    const float* A  = g_u + (size_t)m0*DKD;
    const float* Bp = g_W + (size_t)(l*HH + h)*DKD*DKD;
    ull acc[8][4];
#pragma unroll
    for (int i=0;i<8;i++)
#pragma unroll
        for (int q=0;q<4;q++) acc[i][q]=0ull;
    gemm128<false>(A, Bp, As, Bs, acc, tid);
    int tx = tid & 15, ty = tid >> 4;
    float* Cp = g_T1 + (size_t)h*BSD + (size_t)m0*DKD;
#pragma unroll
    for (int i=0;i<8;i++) {
        int r = ty*8+i;
#pragma unroll
        for (int q=0;q<4;q++) {
            float lo, hi; unpack2(acc[i][q], lo, hi);
            *(float2*)&Cp[r*DKD + tx*8 + 2*q] = make_float2(lo, hi);
        }
    }
}

// ---------------- V = h @ Vw[l,h]^T + Vb  (NT, bias) ------------------------
__global__ __launch_bounds__(256,1) void k_vproj(const float* __restrict__ Vw,
                                                 const float* __restrict__ Vb, int l)
{
    __shared__ float As[8][132], Bs[8][132];
    int tid = threadIdx.x;
    int m0 = blockIdx.x * 128;
    int h = blockIdx.y;
    const float* A    = g_h + (size_t)m0*DKD;
    const float* Bp   = Vw + (size_t)(l*HH + h)*DKD*DKD;
    const float* bias = Vb + (size_t)(l*HH + h)*DKD;
    ull acc[8][4];
#pragma unroll
    for (int i=0;i<8;i++)
#pragma unroll
        for (int q=0;q<4;q++) acc[i][q]=0ull;
    gemm128<true>(A, Bp, As, Bs, acc, tid);
    int tx = tid & 15, ty = tid >> 4;
    float* Cp = g_V + (size_t)h*BSD + (size_t)m0*DKD;
#pragma unroll
    for (int i=0;i<8;i++) {
        int r = ty*8+i;
#pragma unroll
        for (int q=0;q<4;q++) {
            float lo, hi; unpack2(acc[i][q], lo, hi);
            int c0 = tx*8 + 2*q;
            *(float2*)&Cp[r*DKD + c0] = make_float2(lo + bias[c0], hi + bias[c0+1]);
        }
    }
}

// ---------------- M = T1 @ u^T -> A -> softmax -> Pm  (per b,h) -------------
__global__ __launch_bounds__(256,1) void k_attn()
{
    int b = blockIdx.x, h = blockIdx.y;
    __shared__ float As[8][132], Bs[8][132];
    __shared__ float red[128][17];
    __shared__ float rowred[128];
    int tid = threadIdx.x, tx = tid & 15, ty = tid >> 4;
    const float* A  = g_T1 + (size_t)h*BSD + (size_t)b*SS*DKD;
    const float* Bp = g_u + (size_t)b*SS*DKD;
    ull acc[8][4];
#pragma unroll
    for (int i=0;i<8;i++)
#pragma unroll
        for (int q=0;q<4;q++) acc[i][q]=0ull;
    gemm128<true>(A, Bp, As, Bs, acc, tid);

    const float* nr = g_nrm + b*SS;
    float ns[8], nt[8];
#pragma unroll
    for (int i=0;i<8;i++) ns[i] = nr[ty*8+i];
#pragma unroll
    for (int j=0;j<8;j++) nt[j] = nr[tx*8+j];
    const float scale = 0.08838834764831845f;   // 1/sqrt(128)
    float f[8][8];
#pragma unroll
    for (int i=0;i<8;i++)
#pragma unroll
        for (int q=0;q<4;q++) {
            float lo, hi; unpack2(acc[i][q], lo, hi);
            f[i][2*q]   = lo*lo * ns[i]*nt[2*q]   * scale;
            f[i][2*q+1] = hi*hi * ns[i]*nt[2*q+1] * scale;
        }
    // row max
#pragma unroll
    for (int i=0;i<8;i++) {
        float m = f[i][0];
#pragma unroll
        for (int j=1;j<8;j++) m = fmaxf(m, f[i][j]);
        red[ty*8+i][tx] = m;
    }
    __syncthreads();
    if (tid < 128) {
        float m = red[tid][0];
#pragma unroll
        for (int xx=1;xx<16;xx++) m = fmaxf(m, red[tid][xx]);
        rowred[tid] = m;
    }
    __syncthreads();
#pragma unroll
    for (int i=0;i<8;i++) {
        float rm = rowred[ty*8+i];
        float s = 0.0f;
#pragma unroll
        for (int j=0;j<8;j++) { f[i][j] = __expf(f[i][j]-rm); s += f[i][j]; }
        red[ty*8+i][tx] = s;
    }
    __syncthreads();
    if (tid < 128) {
        float s = 0.0f;
#pragma unroll
        for (int xx=0;xx<16;xx++) s += red[tid][xx];
        rowred[tid] = 1.0f / s;
    }
    __syncthreads();
    float* Pp = g_Pm + (size_t)h*BS*SS + (size_t)b*SS*SS;
#pragma unroll
    for (int i=0;i<8;i++) {
        int r = ty*8+i;
        float inv = rowred[r];
#pragma unroll
        for (int q=0;q<4;q++)
            *(float2*)&Pp[r*SS + tx*8 + 2*q] = make_float2(f[i][2*q]*inv, f[i][2*q+1]*inv);
    }
}

// ---------------- hs = LN(Pm@V + h) * merger_w  (per b,h) -------------------
__global__ __launch_bounds__(256,1) void k_pmv(const float* __restrict__ lng,
                                               const float* __restrict__ lnb,
                                               const float* __restrict__ mw, int l)
{
    int b = blockIdx.x, h = blockIdx.y;
    __shared__ float As[8][132], Bs[8][132];
    __shared__ float red[128][17];
    __shared__ float rmean[128];
    __shared__ float rvar[128];
    int tid = threadIdx.x, tx = tid & 15, ty = tid >> 4;
    const float* A  = g_Pm + (size_t)h*BS*SS + (size_t)b*SS*SS;
    const float* Bp = g_V + (size_t)h*BSD + (size_t)b*SS*DKD;
    ull acc[8][4];
#pragma unroll
    for (int i=0;i<8;i++)
#pragma unroll
        for (int q=0;q<4;q++) acc[i][q]=0ull;
    gemm128<false>(A, Bp, As, Bs, acc, tid);

    const float* hb = g_h + (size_t)b*SS*DKD;
    float f[8][8];
#pragma unroll
    for (int i=0;i<8;i++) {
        int r = ty*8+i;
#pragma unroll
        for (int q=0;q<4;q++) {
            float lo, hi; unpack2(acc[i][q], lo, hi);
            int c0 = tx*8+2*q;
            f[i][2*q]   = lo + hb[r*DKD + c0];
            f[i][2*q+1] = hi + hb[r*DKD + c0+1];
        }
    }
    // mean
#pragma unroll
    for (int i=0;i<8;i++) {
        float s = 0.0f;
#pragma unroll
        for (int j=0;j<8;j++) s += f[i][j];
        red[ty*8+i][tx] = s;
    }
    __syncthreads();
    if (tid < 128) {
        float s = 0.0f;
#pragma unroll
        for (int xx=0;xx<16;xx++) s += red[tid][xx];
        rmean[tid] = s * (1.0f/DKD);
    }
    __syncthreads();
    // var (two-pass, matches reference mean((x-m)^2))
#pragma unroll
    for (int i=0;i<8;i++) {
        float m = rmean[ty*8+i];
        float s = 0.0f;
#pragma unroll
        for (int j=0;j<8;j++) { float d = f[i][j]-m; s += d*d; }
        red[ty*8+i][tx] = s;
    }
    __syncthreads();
    if (tid < 128) {
        float s = 0.0f;
#pragma unroll
        for (int xx=0;xx<16;xx++) s += red[tid][xx];
        rvar[tid] = s * (1.0f/DKD);
    }
    __syncthreads();
    const float* gp = lng + (size_t)(l*HH+h)*DKD;
    const float* bp = lnb + (size_t)(l*HH+h)*DKD;
    float mwv = mw[l*HH + h];
    float* Cp = g_hs + (size_t)h*BSD + (size_t)b*SS*DKD;
#pragma unroll
    for (int i=0;i<8;i++) {
        int r = ty*8+i;
        float m = rmean[r];
        float inv = rsqrtf(rvar[r] + 1e-5f);
#pragma unroll
        for (int q=0;q<4;q++) {
            int c0 = tx*8+2*q;
            float o0 = ((f[i][2*q]  -m)*inv*gp[c0]   + bp[c0]  ) * mwv;
            float o1 = ((f[i][2*q+1]-m)*inv*gp[c0+1] + bp[c0+1]) * mwv;
            *(float2*)&Cp[r*DKD + c0] = make_float2(o0, o1);
        }
    }
}

// ---------------- merge heads -----------------------------------------------
__global__ void k_merge(const float* __restrict__ mb, int l)
{
    int i = blockIdx.x*blockDim.x + threadIdx.x;
    if (i < BSD) {
        float a = mb[l];
#pragma unroll
        for (int h = 0; h < HH; h++) a += g_hs[(size_t)h*BSD + i];
        g_h[i] = a;
    }
}

// ---------------- extract last token ----------------------------------------
__global__ void k_extract(float* __restrict__ out)
{
    int i = blockIdx.x*blockDim.x + threadIdx.x;
    if (i < BATCH*DKD) {
        int b = i >> 7, d = i & 127;
        out[i] = g_h[((size_t)b*SS + (SS-1))*DKD + d];
    }
}

// ---------------- launch ----------------------------------------------------
extern "C" void kernel_launch(void* const* d_in, const int* in_sizes, int n_in,
                              void* d_out, int out_size)
{
    const float* x        = (const float*)d_in[0];
    const float* embed_w  = (const float*)d_in[1];
    const float* embed_b  = (const float*)d_in[2];
    const float* class_tk = (const float*)d_in[3];
    const float* norm0_g  = (const float*)d_in[4];
    const float* norm0_b  = (const float*)d_in[5];
    const float* Vw       = (const float*)d_in[6];
    const float* Vb       = (const float*)d_in[7];
    const float* ln_g     = (const float*)d_in[8];
    const float* ln_b     = (const float*)d_in[9];
    const float* phi      = (const float*)d_in[10];
    const float* merger_w = (const float*)d_in[11];
    const float* merger_b = (const float*)d_in[12];
    float* out = (float*)d_out;

    k_embed<<<BS, 128>>>(x, embed_w, embed_b, class_tk, norm0_g, norm0_b);
    k_cs<<<(LHN*PP + 255)/256, 256>>>(phi);
    k_wbuild<<<dim3(LHN, 4), 256>>>();

    for (int l = 0; l < LL; l++) {
        k_norm<<<BS, 128>>>();
        k_t1<<<dim3(BS/128, HH), 256>>>(l);
        k_vproj<<<dim3(BS/128, HH), 256>>>(Vw, Vb, l);
        k_attn<<<dim3(BATCH, HH), 256>>>();
        k_pmv<<<dim3(BATCH, HH), 256>>>(ln_g, ln_b, merger_w, l);
        k_merge<<<(BSD + 255)/256, 256>>>(merger_b, l);
    }
    k_extract<<<(BATCH*DKD + 255)/256, 256>>>(out);
}

// round 4
// speedup vs baseline: 1.6836x; 1.6836x over previous
#include <cuda_runtime.h>
#include <cuda_bf16.h>
#include <cstdint>
#include <math.h>

#define BATCH 128
#define TT    127
#define SS    128
#define DIN   48
#define DKD   128
#define HH    8
#define LL    6
#define PP    8128
#define LHN   48
#define BS    (BATCH*SS)     /* 16384 */
#define BSD   (BS*DKD)       /* 2097152 */

typedef __nv_bfloat16 bf16;

// ---------------- scratch ----------------------------------------------------
__device__ float g_h[BSD];
__device__ float g_nrm[BS];
__device__ float g_cosv[LHN*PP];
__device__ float g_sinv[LHN*PP];
__device__ bf16  g_uhi[BSD],  g_ulo[BSD];
__device__ bf16  g_hhi[BSD],  g_hlo[BSD];
__device__ bf16  g_Wthi[LHN*DKD*DKD], g_Wtlo[LHN*DKD*DKD];
__device__ bf16  g_Vwhi[LHN*DKD*DKD], g_Vwlo[LHN*DKD*DKD];
__device__ bf16  g_T1hi[(size_t)HH*BSD], g_T1lo[(size_t)HH*BSD];
__device__ bf16  g_Pmhi[(size_t)HH*BSD], g_Pmlo[(size_t)HH*BSD];
__device__ bf16  g_Vthi[(size_t)HH*BSD], g_Vtlo[(size_t)HH*BSD];
__device__ float g_hs[(size_t)HH*BSD];

// ---------------- helpers -----------------------------------------------------
__device__ __forceinline__ uint32_t smem_u32(const void* p) {
    uint32_t a;
    asm("{ .reg .u64 t; cvta.to.shared.u64 t, %1; cvt.u32.u64 %0, t; }" : "=r"(a) : "l"(p));
    return a;
}
__device__ __forceinline__ void split2(float x, bf16& h, bf16& l)
{
    h = __float2bfloat16_rn(x);
    l = __float2bfloat16_rn(x - __bfloat162float(h));
}
__device__ __forceinline__ void ldmx4(uint32_t* r, uint32_t addr)
{
    asm volatile("ldmatrix.sync.aligned.m8n8.x4.shared.b16 {%0,%1,%2,%3}, [%4];"
        : "=r"(r[0]), "=r"(r[1]), "=r"(r[2]), "=r"(r[3]) : "r"(addr));
}
__device__ __forceinline__ void ldmx2(uint32_t* r, uint32_t addr)
{
    asm volatile("ldmatrix.sync.aligned.m8n8.x2.shared.b16 {%0,%1}, [%2];"
        : "=r"(r[0]), "=r"(r[1]) : "r"(addr));
}
__device__ __forceinline__ void mma16816(float* d, const uint32_t* a, const uint32_t* b)
{
    asm volatile("mma.sync.aligned.m16n8k16.row.col.f32.bf16.bf16.f32 "
        "{%0,%1,%2,%3}, {%4,%5,%6,%7}, {%8,%9}, {%0,%1,%2,%3};"
        : "+f"(d[0]), "+f"(d[1]), "+f"(d[2]), "+f"(d[3])
        : "r"(a[0]), "r"(a[1]), "r"(a[2]), "r"(a[3]), "r"(b[0]), "r"(b[1]));
}

// ---------------- embed + class token + LN0 ---------------------------------
__global__ void k_embed(const float* __restrict__ x, const float* __restrict__ ew,
                        const float* __restrict__ eb, const float* __restrict__ ct,
                        const float* __restrict__ g0, const float* __restrict__ b0)
{
    int bx = blockIdx.x;
    int b = bx >> 7, s = bx & 127;
    int d = threadIdx.x;
    __shared__ float xs[DIN];
    __shared__ float red[8];
    float v;
    if (s == 0) {
        v = ct[d];
    } else {
        if (d < DIN) xs[d] = x[(b*TT + (s-1))*DIN + d];
        __syncthreads();
        float acc = eb[d];
        const float* wrow = ew + d*DIN;
#pragma unroll
        for (int f = 0; f < DIN; f++) acc += xs[f]*wrow[f];
        v = acc;
    }
    float sum = v, sq = v*v;
#pragma unroll
    for (int o = 16; o; o >>= 1) {
        sum += __shfl_xor_sync(0xffffffffu, sum, o);
        sq  += __shfl_xor_sync(0xffffffffu, sq,  o);
    }
    if ((d & 31) == 0) { red[d>>5] = sum; red[4 + (d>>5)] = sq; }
    __syncthreads();
    float ts = red[0]+red[1]+red[2]+red[3];
    float tq = red[4]+red[5]+red[6]+red[7];
    float mean = ts * (1.0f/DKD);
    float var  = tq * (1.0f/DKD) - mean*mean;
    float inv  = rsqrtf(var + 1e-5f);
    g_h[(size_t)bx*DKD + d] = (v - mean)*inv*g0[d] + b0[d];
}

// ---------------- sincos precompute ------------------------------------------
__global__ void k_cs(const float* __restrict__ phi)
{
    int i = blockIdx.x*blockDim.x + threadIdx.x;
    if (i < LHN*PP) {
        float s, c;
        sincosf(phi[i], &s, &c);
        g_cosv[i] = c; g_sinv[i] = s;
    }
}

// ---------------- split Vw ----------------------------------------------------
__global__ void k_splitVw(const float* __restrict__ Vw)
{
    int i = blockIdx.x*blockDim.x + threadIdx.x;
    if (i < LHN*DKD*DKD) {
        bf16 h, l; split2(Vw[i], h, l);
        g_Vwhi[i] = h; g_Vwlo[i] = l;
    }
}

// ---------------- W build: brick-wall Givens pyramid -> transposed splits ----
__global__ __launch_bounds__(256) void k_wbuild()
{
    int lh = blockIdx.x, cg = blockIdx.y;      // 48 x 4
    __shared__ float Wsh[SS][33];
    int tid = threadIdx.x;
    int col = tid & 31, slot = tid >> 5;
    for (int idx = tid; idx < SS*32; idx += 256) {
        int r = idx >> 5, c = idx & 31;
        Wsh[r][c] = (r == cg*32 + c) ? 1.0f : 0.0f;
    }
    __syncthreads();
    const float* cb = g_cosv + lh*PP;
    const float* sb = g_sinv + lh*PP;
    for (int t = 0; t <= 2*(SS-2); t++) {
        int par  = t & 1;
        int imax = min(t, 2*(SS-2) - t);
        int cnt  = ((imax - par) >> 1) + 1;
        for (int r = slot; r < cnt; r += 8) {
            int i = par + 2*r;
            int k = (t + i) >> 1;
            int p = ((k*(k+1)) >> 1) + k - i;
            float c = cb[p], s = sb[p];
            float ra = Wsh[i][col], rb = Wsh[i+1][col];
            Wsh[i][col]   = c*ra - s*rb;
            Wsh[i+1][col] = s*ra + c*rb;
        }
        __syncthreads();
    }
    // write W transposed (B operand of NT GEMM) as bf16 hi/lo splits
    for (int idx = tid; idx < 32*SS; idx += 256) {
        int r = idx & 127, c = idx >> 7;        // r = wire/row, c = 0..31
        float v = Wsh[r][c];
        bf16 hi, lo; split2(v, hi, lo);
        size_t o = (size_t)lh*DKD*DKD + (size_t)(cg*32 + c)*DKD + r;
        g_Wthi[o] = hi; g_Wtlo[o] = lo;
    }
}

// ---------------- per-layer token norms + splits ------------------------------
__global__ void k_norm()
{
    int row = blockIdx.x;
    int d = threadIdx.x;
    float v = g_h[(size_t)row*DKD + d];
    float sq = v*v;
#pragma unroll
    for (int o = 16; o; o >>= 1) sq += __shfl_xor_sync(0xffffffffu, sq, o);
    __shared__ float red[4];
    if ((d & 31) == 0) red[d>>5] = sq;
    __syncthreads();
    float nrm = sqrtf(red[0]+red[1]+red[2]+red[3]);
    float u = v / nrm;
    size_t o = (size_t)row*DKD + d;
    bf16 hi, lo;
    split2(u, hi, lo); g_uhi[o] = hi; g_ulo[o] = lo;
    split2(v, hi, lo); g_hhi[o] = hi; g_hlo[o] = lo;
    if (d == 0) g_nrm[row] = nrm;
}

// ---------------- HMMA bf16x3 GEMM with fused epilogues -----------------------
// SMEM (bytes from dynamic base, 16B aligned):
#define TSTRIDE 136                       /* bf16 elems per row (128 + 8 pad) */
#define TILE_B  (128*TSTRIDE*2)           /* 34816 */
#define SMO_AHI 0
#define SMO_ALO (TILE_B)
#define SMO_BHI (2*TILE_B)
#define SMO_BLO (3*TILE_B)
#define SMO_F   (4*TILE_B)                /* fsh: 128 floats, fsh2: 128 floats */
#define SMEM_TOTAL (4*TILE_B + 1024)
#define CSTRIDE 129                       /* fp32 staging stride (conflict-free) */

__device__ __forceinline__ void load_tile(const bf16* __restrict__ g, bf16* s, int tid)
{
#pragma unroll
    for (int it = 0; it < 8; it++) {
        int idx = it*256 + tid;            // 2048 chunks of 8 bf16
        int row = idx >> 4, chunk = idx & 15;
        *(uint4*)(s + row*TSTRIDE + chunk*8) = *(const uint4*)(g + row*DKD + chunk*8);
    }
}

__device__ __forceinline__ void split_store8(bf16* dh, bf16* dl, const float* f8)
{
    __align__(16) bf16 th[8], tl[8];
#pragma unroll
    for (int j = 0; j < 8; j++) split2(f8[j], th[j], tl[j]);
    *(uint4*)dh = *(const uint4*)th;
    *(uint4*)dl = *(const uint4*)tl;
}

// MODE 0: T1 = u @ W           -> T1 splits
// MODE 1: V  = h @ Vw^T + b    -> Vt splits (transposed)
// MODE 2: M  = T1 @ u^T -> A -> softmax -> Pm splits
// MODE 3: O  = Pm @ Vt^T + res -> LN -> *mw -> g_hs
template<int MODE>
__global__ void __launch_bounds__(256, 1) k_gemm(int l,
    const float* __restrict__ Vb, const float* __restrict__ lng,
    const float* __restrict__ lnb, const float* __restrict__ mw)
{
    extern __shared__ char sm[];
    uint32_t smb = smem_u32(sm);

    int bx = blockIdx.x;                 // m-tile == batch index
    int h  = blockIdx.y;
    int tid = threadIdx.x, lane = tid & 31, wid = tid >> 5;
    int wm = wid >> 2, wn = wid & 3;

    float* fsh  = (float*)(sm + SMO_F);
    float* fsh2 = fsh + 128;

    const bf16 *Ah, *Al, *Bh, *Bl;
    size_t hb = (size_t)h*BS + (size_t)bx*128;      // token base within [h] arrays
    if (MODE == 0) {
        Ah = g_uhi + (size_t)bx*128*DKD;  Al = g_ulo + (size_t)bx*128*DKD;
        Bh = g_Wthi + (size_t)(l*HH+h)*DKD*DKD; Bl = g_Wtlo + (size_t)(l*HH+h)*DKD*DKD;
    } else if (MODE == 1) {
        Ah = g_hhi + (size_t)bx*128*DKD;  Al = g_hlo + (size_t)bx*128*DKD;
        Bh = g_Vwhi + (size_t)(l*HH+h)*DKD*DKD; Bl = g_Vwlo + (size_t)(l*HH+h)*DKD*DKD;
    } else if (MODE == 2) {
        Ah = g_T1hi + hb*DKD; Al = g_T1lo + hb*DKD;
        Bh = g_uhi + (size_t)bx*128*DKD;  Bl = g_ulo + (size_t)bx*128*DKD;
    } else {
        Ah = g_Pmhi + hb*DKD; Al = g_Pmlo + hb*DKD;
        Bh = g_Vthi + hb*DKD; Bl = g_Vtlo + hb*DKD;
    }

    load_tile(Ah, (bf16*)(sm + SMO_AHI), tid);
    load_tile(Al, (bf16*)(sm + SMO_ALO), tid);
    load_tile(Bh, (bf16*)(sm + SMO_BHI), tid);
    load_tile(Bl, (bf16*)(sm + SMO_BLO), tid);

    if (MODE == 1 && tid < 128) fsh[tid] = Vb[(l*HH+h)*DKD + tid];
    if (MODE == 2 && tid < 128) fsh[tid] = g_nrm[bx*128 + tid];
    if (MODE == 3 && tid < 128) {
        fsh[tid]  = lng[(size_t)(l*HH+h)*DKD + tid];
        fsh2[tid] = lnb[(size_t)(l*HH+h)*DKD + tid];
    }
    __syncthreads();

    // per-lane ldmatrix byte offsets (within a tile)
    uint32_t aoff[4], boff[4];
#pragma unroll
    for (int mi = 0; mi < 4; mi++)
        aoff[mi] = ((wm*64 + mi*16 + (lane & 15))*TSTRIDE + (lane >> 4)*8) * 2;
#pragma unroll
    for (int nj = 0; nj < 4; nj++)
        boff[nj] = ((wn*32 + nj*8 + (lane & 7))*TSTRIDE + ((lane >> 3) & 1)*8) * 2;

    float acc[4][4][4];
#pragma unroll
    for (int mi = 0; mi < 4; mi++)
#pragma unroll
        for (int nj = 0; nj < 4; nj++)
#pragma unroll
            for (int q = 0; q < 4; q++) acc[mi][nj][q] = 0.0f;

#pragma unroll
    for (int kk = 0; kk < 8; kk++) {
        uint32_t k2 = kk*32;             // 16 bf16 = 32 bytes
        uint32_t ah[4][4], al[4][4], bh[4][2], bl[4][2];
#pragma unroll
        for (int mi = 0; mi < 4; mi++) {
            ldmx4(ah[mi], smb + SMO_AHI + aoff[mi] + k2);
            ldmx4(al[mi], smb + SMO_ALO + aoff[mi] + k2);
        }
#pragma unroll
        for (int nj = 0; nj < 4; nj++) {
            ldmx2(bh[nj], smb + SMO_BHI + boff[nj] + k2);
            ldmx2(bl[nj], smb + SMO_BLO + boff[nj] + k2);
        }
#pragma unroll
        for (int mi = 0; mi < 4; mi++)
#pragma unroll
            for (int nj = 0; nj < 4; nj++) {
                mma16816(acc[mi][nj], ah[mi], bh[nj]);
                mma16816(acc[mi][nj], al[mi], bh[nj]);
                mma16816(acc[mi][nj], ah[mi], bl[nj]);
            }
    }

    __syncthreads();                      // done reading A/B smem; reuse as Cs

    // stage C into smem fp32, stride 129 (conflict-free row AND col access)
    float* Cs = (float*)sm;
    {
        int gid = lane >> 2, tig = lane & 3;
#pragma unroll
        for (int mi = 0; mi < 4; mi++) {
            int r0 = wm*64 + mi*16 + gid;
#pragma unroll
            for (int nj = 0; nj < 4; nj++) {
                int c0 = wn*32 + nj*8 + tig*2;
                Cs[r0*CSTRIDE + c0]       = acc[mi][nj][0];
                Cs[r0*CSTRIDE + c0 + 1]   = acc[mi][nj][1];
                Cs[(r0+8)*CSTRIDE + c0]     = acc[mi][nj][2];
                Cs[(r0+8)*CSTRIDE + c0 + 1] = acc[mi][nj][3];
            }
        }
    }
    __syncthreads();

    if (tid < 128) {
        if (MODE == 0) {
            size_t base = (hb + tid) * DKD;
#pragma unroll
            for (int c0 = 0; c0 < 128; c0 += 8) {
                float f8[8];
#pragma unroll
                for (int j = 0; j < 8; j++) f8[j] = Cs[tid*CSTRIDE + c0 + j];
                split_store8(g_T1hi + base + c0, g_T1lo + base + c0, f8);
            }
        }
        else if (MODE == 1) {              // transposed store: thread owns col d
            float vb = fsh[tid];
            size_t base = (hb + tid) * DKD;  // Vt row d
#pragma unroll
            for (int s0 = 0; s0 < 128; s0 += 8) {
                float f8[8];
#pragma unroll
                for (int j = 0; j < 8; j++) f8[j] = Cs[(s0+j)*CSTRIDE + tid] + vb;
                split_store8(g_Vthi + base + s0, g_Vtlo + base + s0, f8);
            }
        }
        else if (MODE == 2) {
            const float scale = 0.08838834764831845f;    // 1/sqrt(128)
            float ns = fsh[tid] * scale;
            float m = -1e30f;
#pragma unroll
            for (int c = 0; c < 128; c++) {
                float t = Cs[tid*CSTRIDE + c];
                t = t*t * ns * fsh[c];
                Cs[tid*CSTRIDE + c] = t;
                m = fmaxf(m, t);
            }
            float s = 0.0f;
#pragma unroll
            for (int c = 0; c < 128; c++) {
                float e = __expf(Cs[tid*CSTRIDE + c] - m);
                Cs[tid*CSTRIDE + c] = e;
                s += e;
            }
            float inv = 1.0f / s;
            size_t base = (hb + tid) * DKD;
#pragma unroll
            for (int c0 = 0; c0 < 128; c0 += 8) {
                float f8[8];
#pragma unroll
                for (int j = 0; j < 8; j++) f8[j] = Cs[tid*CSTRIDE + c0 + j] * inv;
                split_store8(g_Pmhi + base + c0, g_Pmlo + base + c0, f8);
            }
        }
        else {  // MODE 3
            const float* hr = g_h + (size_t)(bx*128 + tid)*DKD;
            float s = 0.0f;
#pragma unroll
            for (int c0 = 0; c0 < 128; c0 += 4) {
                float4 r4 = *(const float4*)(hr + c0);
                float v0 = Cs[tid*CSTRIDE + c0]     + r4.x;
                float v1 = Cs[tid*CSTRIDE + c0 + 1] + r4.y;
                float v2 = Cs[tid*CSTRIDE + c0 + 2] + r4.z;
                float v3 = Cs[tid*CSTRIDE + c0 + 3] + r4.w;
                Cs[tid*CSTRIDE + c0]     = v0;
                Cs[tid*CSTRIDE + c0 + 1] = v1;
                Cs[tid*CSTRIDE + c0 + 2] = v2;
                Cs[tid*CSTRIDE + c0 + 3] = v3;
                s += v0 + v1 + v2 + v3;
            }
            float mean = s * (1.0f/DKD);
            float vv = 0.0f;
#pragma unroll
            for (int c = 0; c < 128; c++) {
                float d = Cs[tid*CSTRIDE + c] - mean;
                vv += d*d;
            }
            float inv = rsqrtf(vv*(1.0f/DKD) + 1e-5f);
            float mwv = mw[l*HH + h];
            float* op = g_hs + (hb + tid)*DKD;
#pragma unroll
            for (int c0 = 0; c0 < 128; c0 += 4) {
                float4 o;
                o.x = ((Cs[tid*CSTRIDE+c0]  -mean)*inv*fsh[c0]   + fsh2[c0]  ) * mwv;
                o.y = ((Cs[tid*CSTRIDE+c0+1]-mean)*inv*fsh[c0+1] + fsh2[c0+1]) * mwv;
                o.z = ((Cs[tid*CSTRIDE+c0+2]-mean)*inv*fsh[c0+2] + fsh2[c0+2]) * mwv;
                o.w = ((Cs[tid*CSTRIDE+c0+3]-mean)*inv*fsh[c0+3] + fsh2[c0+3]) * mwv;
                *(float4*)(op + c0) = o;
            }
        }
    }
}

// ---------------- merge heads -------------------------------------------------
__global__ void k_merge(const float* __restrict__ mb, int l)
{
    int i = blockIdx.x*blockDim.x + threadIdx.x;
    if (i < BSD) {
        float a = mb[l];
#pragma unroll
        for (int h = 0; h < HH; h++) a += g_hs[(size_t)h*BSD + i];
        g_h[i] = a;
    }
}

// ---------------- extract last token ------------------------------------------
__global__ void k_extract(float* __restrict__ out)
{
    int i = blockIdx.x*blockDim.x + threadIdx.x;
    if (i < BATCH*DKD) {
        int b = i >> 7, d = i & 127;
        out[i] = g_h[((size_t)b*SS + (SS-1))*DKD + d];
    }
}

// ---------------- launch ------------------------------------------------------
extern "C" void kernel_launch(void* const* d_in, const int* in_sizes, int n_in,
                              void* d_out, int out_size)
{
    const float* x        = (const float*)d_in[0];
    const float* embed_w  = (const float*)d_in[1];
    const float* embed_b  = (const float*)d_in[2];
    const float* class_tk = (const float*)d_in[3];
    const float* norm0_g  = (const float*)d_in[4];
    const float* norm0_b  = (const float*)d_in[5];
    const float* Vw       = (const float*)d_in[6];
    const float* Vb       = (const float*)d_in[7];
    const float* ln_g     = (const float*)d_in[8];
    const float* ln_b     = (const float*)d_in[9];
    const float* phi      = (const float*)d_in[10];
    const float* merger_w = (const float*)d_in[11];
    const float* merger_b = (const float*)d_in[12];
    float* out = (float*)d_out;

    static int smem_set = 0;
    if (!smem_set) {
        cudaFuncSetAttribute(k_gemm<0>, cudaFuncAttributeMaxDynamicSharedMemorySize, SMEM_TOTAL);
        cudaFuncSetAttribute(k_gemm<1>, cudaFuncAttributeMaxDynamicSharedMemorySize, SMEM_TOTAL);
        cudaFuncSetAttribute(k_gemm<2>, cudaFuncAttributeMaxDynamicSharedMemorySize, SMEM_TOTAL);
        cudaFuncSetAttribute(k_gemm<3>, cudaFuncAttributeMaxDynamicSharedMemorySize, SMEM_TOTAL);
        smem_set = 1;
    }

    k_embed<<<BS, 128>>>(x, embed_w, embed_b, class_tk, norm0_g, norm0_b);
    k_cs<<<(LHN*PP + 255)/256, 256>>>(phi);
    k_wbuild<<<dim3(LHN, 4), 256>>>();
    k_splitVw<<<(LHN*DKD*DKD + 255)/256, 256>>>(Vw);

    dim3 gg(BATCH, HH);
    for (int l = 0; l < LL; l++) {
        k_norm<<<BS, 128>>>();
        k_gemm<0><<<gg, 256, SMEM_TOTAL>>>(l, Vb, ln_g, ln_b, merger_w);
        k_gemm<1><<<gg, 256, SMEM_TOTAL>>>(l, Vb, ln_g, ln_b, merger_w);
        k_gemm<2><<<gg, 256, SMEM_TOTAL>>>(l, Vb, ln_g, ln_b, merger_w);
        k_gemm<3><<<gg, 256, SMEM_TOTAL>>>(l, Vb, ln_g, ln_b, merger_w);
        k_merge<<<(BSD + 255)/256, 256>>>(merger_b, l);
    }
    k_extract<<<(BATCH*DKD + 255)/256, 256>>>(out);
}

// round 5
// speedup vs baseline: 2.1782x; 1.2938x over previous
#include <cuda_runtime.h>
#include <cuda_bf16.h>
#include <cstdint>
#include <math.h>

#define BATCH 128
#define TT    127
#define SS    128
#define DIN   48
#define DKD   128
#define HH    8
#define LL    6
#define PP    8128
#define LHN   48
#define BS    (BATCH*SS)     /* 16384 */
#define BSD   (BS*DKD)       /* 2097152 */

typedef __nv_bfloat16 bf16;

// ---------------- scratch ----------------------------------------------------
__device__ float g_h[BSD];
__device__ float g_nrm[BS];
__device__ float g_cosv[LHN*PP];
__device__ float g_sinv[LHN*PP];
__device__ bf16  g_uhi[BSD],  g_ulo[BSD];
__device__ bf16  g_hhi[BSD],  g_hlo[BSD];
__device__ bf16  g_Wthi[LHN*DKD*DKD], g_Wtlo[LHN*DKD*DKD];
__device__ bf16  g_Vwhi[LHN*DKD*DKD], g_Vwlo[LHN*DKD*DKD];
__device__ float g_hs[(size_t)HH*BSD];

// ---------------- helpers -----------------------------------------------------
__device__ __forceinline__ uint32_t smem_u32(const void* p) {
    uint32_t a;
    asm("{ .reg .u64 t; cvta.to.shared.u64 t, %1; cvt.u32.u64 %0, t; }" : "=r"(a) : "l"(p));
    return a;
}
__device__ __forceinline__ void split2(float x, bf16& h, bf16& l)
{
    h = __float2bfloat16_rn(x);
    l = __float2bfloat16_rn(x - __bfloat162float(h));
}
__device__ __forceinline__ void ldmx4(uint32_t* r, uint32_t addr)
{
    asm volatile("ldmatrix.sync.aligned.m8n8.x4.shared.b16 {%0,%1,%2,%3}, [%4];"
        : "=r"(r[0]), "=r"(r[1]), "=r"(r[2]), "=r"(r[3]) : "r"(addr));
}
__device__ __forceinline__ void ldmx2(uint32_t* r, uint32_t addr)
{
    asm volatile("ldmatrix.sync.aligned.m8n8.x2.shared.b16 {%0,%1}, [%2];"
        : "=r"(r[0]), "=r"(r[1]) : "r"(addr));
}
__device__ __forceinline__ void mma16816(float* d, const uint32_t* a, const uint32_t* b)
{
    asm volatile("mma.sync.aligned.m16n8k16.row.col.f32.bf16.bf16.f32 "
        "{%0,%1,%2,%3}, {%4,%5,%6,%7}, {%8,%9}, {%0,%1,%2,%3};"
        : "+f"(d[0]), "+f"(d[1]), "+f"(d[2]), "+f"(d[3])
        : "r"(a[0]), "r"(a[1]), "r"(a[2]), "r"(a[3]), "r"(b[0]), "r"(b[1]));
}
#define CP16(dst, src) \
    asm volatile("cp.async.cg.shared.global [%0], [%1], 16;" :: "r"(dst), "l"(src))
#define CP_COMMIT() asm volatile("cp.async.commit_group;" ::: "memory")
#define CP_WAIT0()  asm volatile("cp.async.wait_group 0;" ::: "memory")

// ---------------- embed + class token + LN0 ---------------------------------
__global__ void k_embed(const float* __restrict__ x, const float* __restrict__ ew,
                        const float* __restrict__ eb, const float* __restrict__ ct,
                        const float* __restrict__ g0, const float* __restrict__ b0)
{
    int bx = blockIdx.x;
    int b = bx >> 7, s = bx & 127;
    int d = threadIdx.x;
    __shared__ float xs[DIN];
    __shared__ float red[8];
    float v;
    if (s == 0) {
        v = ct[d];
    } else {
        if (d < DIN) xs[d] = x[(b*TT + (s-1))*DIN + d];
        __syncthreads();
        float acc = eb[d];
        const float* wrow = ew + d*DIN;
#pragma unroll
        for (int f = 0; f < DIN; f++) acc += xs[f]*wrow[f];
        v = acc;
    }
    float sum = v, sq = v*v;
#pragma unroll
    for (int o = 16; o; o >>= 1) {
        sum += __shfl_xor_sync(0xffffffffu, sum, o);
        sq  += __shfl_xor_sync(0xffffffffu, sq,  o);
    }
    if ((d & 31) == 0) { red[d>>5] = sum; red[4 + (d>>5)] = sq; }
    __syncthreads();
    float ts = red[0]+red[1]+red[2]+red[3];
    float tq = red[4]+red[5]+red[6]+red[7];
    float mean = ts * (1.0f/DKD);
    float var  = tq * (1.0f/DKD) - mean*mean;
    float inv  = rsqrtf(var + 1e-5f);
    g_h[(size_t)bx*DKD + d] = (v - mean)*inv*g0[d] + b0[d];
}

// ---------------- sincos precompute ------------------------------------------
__global__ void k_cs(const float* __restrict__ phi)
{
    int i = blockIdx.x*blockDim.x + threadIdx.x;
    if (i < LHN*PP) {
        float s, c;
        sincosf(phi[i], &s, &c);
        g_cosv[i] = c; g_sinv[i] = s;
    }
}

// ---------------- split Vw ----------------------------------------------------
__global__ void k_splitVw(const float* __restrict__ Vw)
{
    int i = blockIdx.x*blockDim.x + threadIdx.x;
    if (i < LHN*DKD*DKD) {
        bf16 h, l; split2(Vw[i], h, l);
        g_Vwhi[i] = h; g_Vwlo[i] = l;
    }
}

// ---------------- W build: brick-wall Givens pyramid -> transposed splits ----
__global__ __launch_bounds__(256) void k_wbuild()
{
    int lh = blockIdx.x, cg = blockIdx.y;      // 48 x 4
    __shared__ float Wsh[SS][33];
    int tid = threadIdx.x;
    int col = tid & 31, slot = tid >> 5;
    for (int idx = tid; idx < SS*32; idx += 256) {
        int r = idx >> 5, c = idx & 31;
        Wsh[r][c] = (r == cg*32 + c) ? 1.0f : 0.0f;
    }
    __syncthreads();
    const float* cb = g_cosv + lh*PP;
    const float* sb = g_sinv + lh*PP;
    for (int t = 0; t <= 2*(SS-2); t++) {
        int par  = t & 1;
        int imax = min(t, 2*(SS-2) - t);
        int cnt  = ((imax - par) >> 1) + 1;
        for (int r = slot; r < cnt; r += 8) {
            int i = par + 2*r;
            int k = (t + i) >> 1;
            int p = ((k*(k+1)) >> 1) + k - i;
            float c = cb[p], s = sb[p];
            float ra = Wsh[i][col], rb = Wsh[i+1][col];
            Wsh[i][col]   = c*ra - s*rb;
            Wsh[i+1][col] = s*ra + c*rb;
        }
        __syncthreads();
    }
    for (int idx = tid; idx < 32*SS; idx += 256) {
        int r = idx & 127, c = idx >> 7;
        float v = Wsh[r][c];
        bf16 hi, lo; split2(v, hi, lo);
        size_t o = (size_t)lh*DKD*DKD + (size_t)(cg*32 + c)*DKD + r;
        g_Wthi[o] = hi; g_Wtlo[o] = lo;
    }
}

// ---------------- token norms + splits (layer-0 prep) -------------------------
__global__ void k_norm()
{
    int row = blockIdx.x;
    int d = threadIdx.x;
    float v = g_h[(size_t)row*DKD + d];
    float sq = v*v;
#pragma unroll
    for (int o = 16; o; o >>= 1) sq += __shfl_xor_sync(0xffffffffu, sq, o);
    __shared__ float red[4];
    if ((d & 31) == 0) red[d>>5] = sq;
    __syncthreads();
    float nrm = sqrtf(red[0]+red[1]+red[2]+red[3]);
    float u = v / nrm;
    size_t o = (size_t)row*DKD + d;
    bf16 hi, lo;
    split2(u, hi, lo); g_uhi[o] = hi; g_ulo[o] = lo;
    split2(v, hi, lo); g_hhi[o] = hi; g_hlo[o] = lo;
    if (d == 0) g_nrm[row] = nrm;
}

// ---------------- merge heads + norms + splits (between layers) ---------------
__global__ void k_mergenorm(const float* __restrict__ mb, int l)
{
    int row = blockIdx.x;
    int d = threadIdx.x;
    size_t o = (size_t)row*DKD + d;
    float a = mb[l];
#pragma unroll
    for (int h = 0; h < HH; h++) a += g_hs[(size_t)h*BSD + o];
    float sq = a*a;
#pragma unroll
    for (int of = 16; of; of >>= 1) sq += __shfl_xor_sync(0xffffffffu, sq, of);
    __shared__ float red[4];
    if ((d & 31) == 0) red[d>>5] = sq;
    __syncthreads();
    float nrm = sqrtf(red[0]+red[1]+red[2]+red[3]);
    g_h[o] = a;
    bf16 hi, lo;
    split2(a/nrm, hi, lo); g_uhi[o] = hi; g_ulo[o] = lo;
    split2(a,     hi, lo); g_hhi[o] = hi; g_hlo[o] = lo;
    if (d == 0) g_nrm[row] = nrm;
}

// ---------------- fused layer kernel ------------------------------------------
#define TSTRIDE 136
#define TILE1   (128*TSTRIDE*2)        /* 34816 bytes, one bf16 tile */
#define RPAIR   (2*TILE1)              /* 69632: hi+lo pair */
#define R1O     0
#define R2O     RPAIR
#define R3O     (2*RPAIR)
#define SMO_F   (3*RPAIR)
#define SMEM_TOTAL (3*RPAIR + 2048)
#define CSTRIDE 129

__device__ __forceinline__ void load_pair_async(uint32_t dst,
    const bf16* __restrict__ hi, const bf16* __restrict__ lo, int tid)
{
#pragma unroll
    for (int it = 0; it < 8; it++) {
        int idx = it*256 + tid;
        int row = idx >> 4, chunk = idx & 15;
        uint32_t so = dst + (row*TSTRIDE + chunk*8)*2;
        CP16(so,         hi + row*DKD + chunk*8);
        CP16(so + TILE1, lo + row*DKD + chunk*8);
    }
}

__device__ __forceinline__ void gemm3(uint32_t aBase, uint32_t bBase,
                                      float acc[4][4][4], int lane, int wm, int wn)
{
    uint32_t aoff[4], boff[4];
#pragma unroll
    for (int mi = 0; mi < 4; mi++)
        aoff[mi] = aBase + ((wm*64 + mi*16 + (lane & 15))*TSTRIDE + (lane >> 4)*8) * 2;
#pragma unroll
    for (int nj = 0; nj < 4; nj++)
        boff[nj] = bBase + ((wn*32 + nj*8 + (lane & 7))*TSTRIDE + ((lane >> 3) & 1)*8) * 2;
#pragma unroll
    for (int mi = 0; mi < 4; mi++)
#pragma unroll
        for (int nj = 0; nj < 4; nj++)
#pragma unroll
            for (int q = 0; q < 4; q++) acc[mi][nj][q] = 0.0f;

#pragma unroll 2
    for (int kk = 0; kk < 8; kk++) {
        uint32_t k2 = kk*32;
        uint32_t ah[4][4], al[4][4], bh[4][2], bl[4][2];
#pragma unroll
        for (int mi = 0; mi < 4; mi++) {
            ldmx4(ah[mi], aoff[mi] + k2);
            ldmx4(al[mi], aoff[mi] + TILE1 + k2);
        }
#pragma unroll
        for (int nj = 0; nj < 4; nj++) {
            ldmx2(bh[nj], boff[nj] + k2);
            ldmx2(bl[nj], boff[nj] + TILE1 + k2);
        }
#pragma unroll
        for (int mi = 0; mi < 4; mi++)
#pragma unroll
            for (int nj = 0; nj < 4; nj++) {
                mma16816(acc[mi][nj], ah[mi], bh[nj]);
                mma16816(acc[mi][nj], al[mi], bh[nj]);
                mma16816(acc[mi][nj], ah[mi], bl[nj]);
            }
    }
}

__device__ __forceinline__ void stageC(float* Cs, float acc[4][4][4],
                                       int lane, int wm, int wn)
{
    int gid = lane >> 2, tig = lane & 3;
#pragma unroll
    for (int mi = 0; mi < 4; mi++) {
        int r0 = wm*64 + mi*16 + gid;
#pragma unroll
        for (int nj = 0; nj < 4; nj++) {
            int c0 = wn*32 + nj*8 + tig*2;
            Cs[r0*CSTRIDE + c0]         = acc[mi][nj][0];
            Cs[r0*CSTRIDE + c0 + 1]     = acc[mi][nj][1];
            Cs[(r0+8)*CSTRIDE + c0]     = acc[mi][nj][2];
            Cs[(r0+8)*CSTRIDE + c0 + 1] = acc[mi][nj][3];
        }
    }
}

// convert accumulator fragments directly into a smem bf16 hi/lo pair tile
__device__ __forceinline__ void fragToTile(char* sm, uint32_t rOff, float acc[4][4][4],
                                           int lane, int wm, int wn)
{
    int gid = lane >> 2, tig = lane & 3;
#pragma unroll
    for (int mi = 0; mi < 4; mi++) {
        int r0 = wm*64 + mi*16 + gid;
#pragma unroll
        for (int nj = 0; nj < 4; nj++) {
            int c0 = wn*32 + nj*8 + tig*2;
#pragma unroll
            for (int half = 0; half < 2; half++) {
                int r = r0 + half*8;
                float v0 = acc[mi][nj][half*2], v1 = acc[mi][nj][half*2+1];
                bf16 h0, l0, h1, l1;
                split2(v0, h0, l0); split2(v1, h1, l1);
                __nv_bfloat162* ph = (__nv_bfloat162*)(sm + rOff + (r*TSTRIDE + c0)*2);
                __nv_bfloat162* pl = (__nv_bfloat162*)(sm + rOff + TILE1 + (r*TSTRIDE + c0)*2);
                *ph = __nv_bfloat162(h0, h1);
                *pl = __nv_bfloat162(l0, l1);
            }
        }
    }
}

__device__ __forceinline__ void splitRow8ToTile(char* sm, uint32_t rOff,
                                                int row, int c0, const float* f8)
{
    __align__(16) bf16 th[8], tl[8];
#pragma unroll
    for (int j = 0; j < 8; j++) split2(f8[j], th[j], tl[j]);
    *(uint4*)(sm + rOff + (row*TSTRIDE + c0)*2)         = *(const uint4*)th;
    *(uint4*)(sm + rOff + TILE1 + (row*TSTRIDE + c0)*2) = *(const uint4*)tl;
}

__global__ void __launch_bounds__(256, 1) k_layer(int l,
    const float* __restrict__ Vb, const float* __restrict__ lng,
    const float* __restrict__ lnb, const float* __restrict__ mw)
{
    extern __shared__ char sm[];
    uint32_t smb = smem_u32(sm);

    int bx = blockIdx.x;                 // batch / m-tile
    int h  = blockIdx.y;
    int tid = threadIdx.x, lane = tid & 31, wid = tid >> 5;
    int wm = wid >> 2, wn = wid & 3;

    float* fnrm = (float*)(sm + SMO_F);
    float* fvb  = fnrm + 128;
    float* fg   = fnrm + 256;
    float* fb   = fnrm + 384;

    size_t tokBase = (size_t)bx*128*DKD;
    size_t lhOff   = (size_t)(l*HH + h)*DKD*DKD;
    size_t hsBase  = (size_t)h*BSD + tokBase;

    // phase 1: load u -> R1, Wt -> R2
    load_pair_async(smb + R1O, g_uhi + tokBase, g_ulo + tokBase, tid);
    load_pair_async(smb + R2O, g_Wthi + lhOff,  g_Wtlo + lhOff,  tid);
    CP_COMMIT();
    if (tid < 128) {
        fnrm[tid] = g_nrm[bx*128 + tid];
        fvb[tid]  = Vb[(l*HH+h)*DKD + tid];
        fg[tid]   = lng[(size_t)(l*HH+h)*DKD + tid];
        fb[tid]   = lnb[(size_t)(l*HH+h)*DKD + tid];
    }
    CP_WAIT0();
    __syncthreads();

    float acc[4][4][4];

    // GEMM1: T1 = u @ W   (A=R1, B=R2)
    gemm3(smb + R1O, smb + R2O, acc, lane, wm, wn);
    fragToTile(sm, R3O, acc, lane, wm, wn);        // T1 splits -> R3
    __syncthreads();

    // GEMM2: M = T1 @ u^T  (A=R3, B=R1)
    gemm3(smb + R3O, smb + R1O, acc, lane, wm, wn);
    __syncthreads();

    // prefetch h -> R3 (T1 consumed)
    load_pair_async(smb + R3O, g_hhi + tokBase, g_hlo + tokBase, tid);
    CP_COMMIT();

    // stage M -> Cs(R2) (W consumed)
    float* Cs2 = (float*)(sm + R2O);
    stageC(Cs2, acc, lane, wm, wn);
    __syncthreads();

    // softmax rows -> Pm splits -> R1 (u consumed)
    if (tid < 128) {
        const float scale = 0.08838834764831845f;    // 1/sqrt(128)
        float* Crow = Cs2 + tid*CSTRIDE;
        float ns = fnrm[tid] * scale;
        float m = -1e30f;
#pragma unroll
        for (int c = 0; c < 128; c++) {
            float t = Crow[c];
            t = t*t * ns * fnrm[c];
            Crow[c] = t;
            m = fmaxf(m, t);
        }
        float s = 0.0f;
#pragma unroll
        for (int c = 0; c < 128; c++) {
            float e = __expf(Crow[c] - m);
            Crow[c] = e;
            s += e;
        }
        float inv = 1.0f / s;
#pragma unroll
        for (int c0 = 0; c0 < 128; c0 += 8) {
            float f8[8];
#pragma unroll
            for (int j = 0; j < 8; j++) f8[j] = Crow[c0+j] * inv;
            splitRow8ToTile(sm, R1O, tid, c0, f8);
        }
    }
    __syncthreads();

    // load Vw -> R2 (Cs consumed)
    load_pair_async(smb + R2O, g_Vwhi + lhOff, g_Vwlo + lhOff, tid);
    CP_COMMIT();
    CP_WAIT0();
    __syncthreads();

    // GEMM3: V = h @ Vw^T  (A=R3, B=R2)
    gemm3(smb + R3O, smb + R2O, acc, lane, wm, wn);
    __syncthreads();

    // stage V -> Cs(R3) (h consumed)
    float* Cs3 = (float*)(sm + R3O);
    stageC(Cs3, acc, lane, wm, wn);
    __syncthreads();

    // convert V^T (+bias) -> R2 splits (Vw consumed)
    if (tid < 128) {
        float vb = fvb[tid];
#pragma unroll
        for (int t0 = 0; t0 < 128; t0 += 8) {
            float f8[8];
#pragma unroll
            for (int j = 0; j < 8; j++) f8[j] = Cs3[(t0+j)*CSTRIDE + tid] + vb;
            splitRow8ToTile(sm, R2O, tid, t0, f8);
        }
    }
    __syncthreads();

    // GEMM4: O = Pm @ V^T  (A=R1, B=R2)
    gemm3(smb + R1O, smb + R2O, acc, lane, wm, wn);
    __syncthreads();

    // stage O -> Cs(R3)
    stageC(Cs3, acc, lane, wm, wn);
    __syncthreads();

    // epilogue: +residual, LayerNorm, * merger_w -> g_hs
    if (tid < 128) {
        float* Crow = Cs3 + tid*CSTRIDE;
        const float* hr = g_h + tokBase + (size_t)tid*DKD;
        float s = 0.0f;
#pragma unroll
        for (int c0 = 0; c0 < 128; c0 += 4) {
            float4 r4 = *(const float4*)(hr + c0);
            float v0 = Crow[c0]   + r4.x;
            float v1 = Crow[c0+1] + r4.y;
            float v2 = Crow[c0+2] + r4.z;
            float v3 = Crow[c0+3] + r4.w;
            Crow[c0] = v0; Crow[c0+1] = v1; Crow[c0+2] = v2; Crow[c0+3] = v3;
            s += v0 + v1 + v2 + v3;
        }
        float mean = s * (1.0f/DKD);
        float vv = 0.0f;
#pragma unroll
        for (int c = 0; c < 128; c++) {
            float d = Crow[c] - mean;
            vv += d*d;
        }
        float inv = rsqrtf(vv*(1.0f/DKD) + 1e-5f);
        float mwv = __ldg(mw + l*HH + h);
        float* op = g_hs + hsBase + (size_t)tid*DKD;
#pragma unroll
        for (int c0 = 0; c0 < 128; c0 += 4) {
            float4 o;
            o.x = ((Crow[c0]  -mean)*inv*fg[c0]   + fb[c0]  ) * mwv;
            o.y = ((Crow[c0+1]-mean)*inv*fg[c0+1] + fb[c0+1]) * mwv;
            o.z = ((Crow[c0+2]-mean)*inv*fg[c0+2] + fb[c0+2]) * mwv;
            o.w = ((Crow[c0+3]-mean)*inv*fg[c0+3] + fb[c0+3]) * mwv;
            *(float4*)(op + c0) = o;
        }
    }
}

// ---------------- extract last token ------------------------------------------
__global__ void k_extract(float* __restrict__ out)
{
    int i = blockIdx.x*blockDim.x + threadIdx.x;
    if (i < BATCH*DKD) {
        int b = i >> 7, d = i & 127;
        out[i] = g_h[((size_t)b*SS + (SS-1))*DKD + d];
    }
}

// ---------------- launch ------------------------------------------------------
extern "C" void kernel_launch(void* const* d_in, const int* in_sizes, int n_in,
                              void* d_out, int out_size)
{
    const float* x        = (const float*)d_in[0];
    const float* embed_w  = (const float*)d_in[1];
    const float* embed_b  = (const float*)d_in[2];
    const float* class_tk = (const float*)d_in[3];
    const float* norm0_g  = (const float*)d_in[4];
    const float* norm0_b  = (const float*)d_in[5];
    const float* Vw       = (const float*)d_in[6];
    const float* Vb       = (const float*)d_in[7];
    const float* ln_g     = (const float*)d_in[8];
    const float* ln_b     = (const float*)d_in[9];
    const float* phi      = (const float*)d_in[10];
    const float* merger_w = (const float*)d_in[11];
    const float* merger_b = (const float*)d_in[12];
    float* out = (float*)d_out;

    static int smem_set = 0;
    if (!smem_set) {
        cudaFuncSetAttribute(k_layer, cudaFuncAttributeMaxDynamicSharedMemorySize, SMEM_TOTAL);
        smem_set = 1;
    }

    k_embed<<<BS, 128>>>(x, embed_w, embed_b, class_tk, norm0_g, norm0_b);
    k_cs<<<(LHN*PP + 255)/256, 256>>>(phi);
    k_wbuild<<<dim3(LHN, 4), 256>>>();
    k_splitVw<<<(LHN*DKD*DKD + 255)/256, 256>>>(Vw);
    k_norm<<<BS, 128>>>();

    dim3 gg(BATCH, HH);
    for (int l = 0; l < LL; l++) {
        k_layer<<<gg, 256, SMEM_TOTAL>>>(l, Vb, ln_g, ln_b, merger_w);
        k_mergenorm<<<BS, 128>>>(merger_b, l);
    }
    k_extract<<<(BATCH*DKD + 255)/256, 256>>>(out);
}